// round 16
// baseline (speedup 1.0000x reference)
#include <cuda_runtime.h>
#include <cuda_fp16.h>
#include <cstdint>

#define HID 128
#define NHEAD 8
#define HD 16
#define MAXN 50000
#define MAXE 500000

typedef unsigned long long ull;

// ---------------- static device scratch ----------------
__device__ float g_q[MAXN * HID];
__device__ __half g_kh[MAXN * HID];           // k fp16 (only consumer: attn)
__device__ __half g_vh[MAXN * HID];           // v fp16
__device__ float g_xr[MAXN * HID];
__device__ float g_num[MAXN * HID];
__device__ float g_z[MAXN * NHEAD];
__device__ __half g_eh[(size_t)MAXE * HID];   // e rows fp16, edge-id order
__device__ int   g_is64;
// CSR by destination
__device__ int g_deg[MAXN];
__device__ int g_off[MAXN + 1];
__device__ int g_pos[MAXN];
__device__ int2 g_se[MAXE];                   // per CSR slot: {src node, edge id}
// 5 weights: hi/lo fp16 blobs, transposed B[n][k], 128x128 swizzled (32KB each)
__device__ __half g_wt[5][2][128 * 128];

// ---------------- helpers ----------------
__device__ __forceinline__ uint32_t smem_u32(const void* p) {
    uint32_t a;
    asm("{ .reg .u64 t; cvta.to.shared.u64 t, %1; cvt.u32.u64 %0, t; }" : "=r"(a) : "l"(p));
    return a;
}

// [128 rows x 128 k] fp16 tile: two 64-k blocks of 16KB, 128B rows, XOR swizzle
__device__ __forceinline__ uint32_t swz(int row, int k) {
    uint32_t off = ((uint32_t)(k >> 6) << 14) + ((uint32_t)row << 7) + ((uint32_t)(k & 63) << 1);
    return off ^ ((off >> 3) & 0x70);
}
// [64 rows x 128 k] fp16 tile: two 64-k blocks of 8KB
__device__ __forceinline__ uint32_t swz64(int row, int k) {
    uint32_t off = ((uint32_t)(k >> 6) << 13) + ((uint32_t)row << 7) + ((uint32_t)(k & 63) << 1);
    return off ^ ((off >> 3) & 0x70);
}

__device__ __forceinline__ void ldsm4(uint32_t* r, uint32_t addr) {
    asm volatile("ldmatrix.sync.aligned.m8n8.x4.shared.b16 {%0,%1,%2,%3}, [%4];"
                 : "=r"(r[0]), "=r"(r[1]), "=r"(r[2]), "=r"(r[3]) : "r"(addr));
}

__device__ __forceinline__ void mma_f16(float* d, const uint32_t* a, uint32_t b0, uint32_t b1) {
    asm("mma.sync.aligned.m16n8k16.row.col.f32.f16.f16.f32 "
        "{%0,%1,%2,%3}, {%4,%5,%6,%7}, {%8,%9}, {%0,%1,%2,%3};"
        : "+f"(d[0]), "+f"(d[1]), "+f"(d[2]), "+f"(d[3])
        : "r"(a[0]), "r"(a[1]), "r"(a[2]), "r"(a[3]), "r"(b0), "r"(b1));
}

// node kernel smem: A 32KB | B-hi 32KB | B-lo 32KB
#define SM_AH 0
#define SM_BH 32768
#define SM_BL 65536
#define SM_TOTAL 98304
// egemm pipe smem: A0 16KB | A1 16KB | B-hi 32KB | B-lo 32KB
#define ESM_A0 0
#define ESM_A1 16384
#define ESM_TOTAL 98304

// ---------------- small kernels ----------------
__global__ void detect_kernel(const void* idx, long long total_elems) {
    if (threadIdx.x == 0 && blockIdx.x == 0) {
        const long long* p = (const long long*)idx;
        long long n = total_elems / 2;
        if (n > 256) n = 256;
        int is64 = 1;
        for (long long i = 0; i < n; i++) {
            long long v = p[i];
            if (v < 0 || v >= (1LL << 31)) is64 = 0;
        }
        g_is64 = is64;
    }
}

__global__ void zero_deg_kernel(int N) {
    int i = blockIdx.x * blockDim.x + threadIdx.x;
    if (i < N) g_deg[i] = 0;
}

__global__ void count_kernel(const void* __restrict__ idx, int E) {
    int e = blockIdx.x * 256 + threadIdx.x;
    if (e >= E) return;
    int d;
    if (g_is64) d = (int)((const long long*)idx)[e + E];
    else        d = ((const int*)idx)[e + E];
    atomicAdd(&g_deg[d], 1);
}

// single-block exclusive scan over g_deg -> g_off, g_pos
__global__ void scan_kernel(int N, int E) {
    __shared__ int sums[1024];
    int t = threadIdx.x;
    int C = (N + 1023) / 1024;
    int b = t * C;
    int hi = b + C; if (hi > N) hi = N;
    int s = 0;
    for (int i = b; i < hi; i++) s += g_deg[i];
    sums[t] = s;
    __syncthreads();
    for (int ofs = 1; ofs < 1024; ofs <<= 1) {
        int v = (t >= ofs) ? sums[t - ofs] : 0;
        __syncthreads();
        sums[t] += v;
        __syncthreads();
    }
    int run = (t == 0) ? 0 : sums[t - 1];
    for (int i = b; i < hi; i++) {
        g_off[i] = run;
        g_pos[i] = run;
        run += g_deg[i];
    }
    if (t == 1023) g_off[N] = E;
}

__global__ void scatter_kernel(const void* __restrict__ idx, int E) {
    int e = blockIdx.x * 256 + threadIdx.x;
    if (e >= E) return;
    int s, d;
    if (g_is64) {
        const long long* p = (const long long*)idx;
        s = (int)p[e]; d = (int)p[e + E];
    } else {
        const int* p = (const int*)idx;
        s = p[e]; d = p[e + E];
    }
    int p = atomicAdd(&g_pos[d], 1);
    g_se[p] = make_int2(s, e);
}

// W ([in=128,out=128] row-major) -> B[n][k]=W[k][n]; fp16 hi/lo; swizzled 128x128 blobs
__global__ void prep_w_kernel(const float* W0, const float* W1, const float* W2,
                              const float* W3, const float* W4) {
    const float* W = W0;
    if (blockIdx.x == 1) W = W1;
    else if (blockIdx.x == 2) W = W2;
    else if (blockIdx.x == 3) W = W3;
    else if (blockIdx.x == 4) W = W4;
    char* hi = (char*)g_wt[blockIdx.x][0];
    char* lo = (char*)g_wt[blockIdx.x][1];
    for (int i = threadIdx.x; i < 128 * 128; i += blockDim.x) {
        int n = i & 127, k = i >> 7;
        float x = W[k * 128 + n];               // coalesced over n
        __half hv = __float2half(x);
        __half lv = __float2half(x - __half2float(hv));
        uint32_t sw = swz(n, k);
        *(__half*)(hi + sw) = hv;
        *(__half*)(lo + sw) = lv;
    }
}

// ---------------- staging ----------------
__device__ __forceinline__ void stage_A(const float* __restrict__ Asrc, int rows_valid,
                                        char* sm, int tid)
{
    char* Ah = sm + SM_AH;
    for (int i = tid; i < 4096; i += 256) {
        int r = i >> 5;
        int c4 = (i & 31) << 2;
        float4 x;
        if (r < rows_valid) x = __ldcs((const float4*)(Asrc + (size_t)r * HID + c4));
        else x = make_float4(0.f, 0.f, 0.f, 0.f);
        __half2 h01 = __floats2half2_rn(x.x, x.y);
        __half2 h23 = __floats2half2_rn(x.z, x.w);
        uint32_t sw = swz(r, c4);
        *(__half2*)(Ah + sw)     = h01;
        *(__half2*)(Ah + sw + 4) = h23;
    }
}

__device__ __forceinline__ void stage_B(int wi, char* sm, int tid)
{
    const float4* sH = (const float4*)g_wt[wi][0];
    const float4* sL = (const float4*)g_wt[wi][1];
    float4* dH = (float4*)(sm + SM_BH);
    float4* dL = (float4*)(sm + SM_BL);
    for (int i = tid; i < 2048; i += 256) { dH[i] = sH[i]; dL[i] = sL[i]; }
}

// ---------------- HMMA mainloop (node): warp tile 64x32, fp16 2-pass ----------------
__device__ __forceinline__ void hmma_loop(uint32_t smb, int lane, int wm, int wn,
                                          float acc[4][4][4])
{
#pragma unroll
    for (int mi = 0; mi < 4; mi++)
#pragma unroll
        for (int nj = 0; nj < 4; nj++)
#pragma unroll
            for (int t = 0; t < 4; t++) acc[mi][nj][t] = 0.f;

    int arow = wm + (lane & 15);
    int acoff = (lane >> 4) << 3;
    int brow = wn + ((lane >> 4) << 3) + (lane & 7);
    int bcoff = lane & 8;

#pragma unroll
    for (int ks = 0; ks < 8; ks++) {
        int k0 = ks * 16;
        uint32_t ahi[4][4];
#pragma unroll
        for (int mi = 0; mi < 4; mi++)
            ldsm4(ahi[mi], smb + SM_AH + swz(arow + mi * 16, k0 + acoff));

        uint32_t bhi[2][4], blo[2][4];
#pragma unroll
        for (int p = 0; p < 2; p++) {
            uint32_t boff = swz(brow + p * 16, k0 + bcoff);
            ldsm4(bhi[p], smb + SM_BH + boff);
            ldsm4(blo[p], smb + SM_BL + boff);
        }

#pragma unroll
        for (int mi = 0; mi < 4; mi++) {
#pragma unroll
            for (int nj = 0; nj < 4; nj++) {
                int p = nj >> 1, hh = (nj & 1) * 2;
                mma_f16(acc[mi][nj], ahi[mi], bhi[p][hh], bhi[p][hh + 1]);
                mma_f16(acc[mi][nj], ahi[mi], blo[p][hh], blo[p][hh + 1]);
            }
        }
    }
}

// ---------------- node kernel: 4 fused projections; k,v stored fp16 ----------------
__global__ __launch_bounds__(256, 2) void node_hmma_kernel(
    const float* __restrict__ X,
    const float* __restrict__ bq, const float* __restrict__ bk,
    const float* __restrict__ bv, const float* __restrict__ bs, int M)
{
    extern __shared__ char sm[];
    uint32_t smb = smem_u32(sm);
    int tid = threadIdx.x;
    int lane = tid & 31, w = tid >> 5;
    int wm = (w >> 2) * 64, wn = (w & 3) * 32;
    int mBase = blockIdx.x * 128;
    int rv = M - mBase; if (rv > 128) rv = 128;

    stage_A(X + (size_t)mBase * HID, rv, sm, tid);

    const float* biases[4] = {bq, bk, bv, bs};

#pragma unroll 1
    for (int wi = 0; wi < 4; wi++) {
        __syncthreads();
        stage_B(wi, sm, tid);
        __syncthreads();

        float acc[4][4][4];
        hmma_loop(smb, lane, wm, wn, acc);

        const float* bias = biases[wi];
        int r0 = mBase + wm + (lane >> 2);
        int cbase = wn + (lane & 3) * 2;
        bool isf16 = (wi == 1 || wi == 2);
        float* outf = (wi == 0) ? g_q : g_xr;
        __half* outh = (wi == 1) ? g_kh : g_vh;
#pragma unroll
        for (int mi = 0; mi < 4; mi++) {
#pragma unroll
            for (int nj = 0; nj < 4; nj++) {
                int c = cbase + nj * 8;
                float b0 = __ldg(bias + c), b1 = __ldg(bias + c + 1);
                int ra = r0 + mi * 16;
                int rb = ra + 8;
                float xa0 = acc[mi][nj][0] + b0, xa1 = acc[mi][nj][1] + b1;
                float xb0 = acc[mi][nj][2] + b0, xb1 = acc[mi][nj][3] + b1;
                if (isf16) {
                    if (ra < M) *(__half2*)(outh + (size_t)ra * HID + c) = __floats2half2_rn(xa0, xa1);
                    if (rb < M) *(__half2*)(outh + (size_t)rb * HID + c) = __floats2half2_rn(xb0, xb1);
                } else {
                    if (ra < M) *(float2*)(outf + (size_t)ra * HID + c) = make_float2(xa0, xa1);
                    if (rb < M) *(float2*)(outf + (size_t)rb * HID + c) = make_float2(xb0, xb1);
                }
            }
        }
    }
}

// ---------------- egemm v2: persistent, double-buffered 64-row tiles ----------------
__global__ __launch_bounds__(256, 2) void egemm_pipe_kernel(
    const float* __restrict__ angle, int E, int numTiles)
{
    extern __shared__ char sm[];
    uint32_t smb = smem_u32(sm);
    int tid = threadIdx.x;
    int lane = tid & 31, w = tid >> 5;
    int wm = (w >> 2) * 32, wn = (w & 3) * 32;

    stage_B(4, sm, tid);    // B resident for the whole kernel

    int arow = wm + (lane & 15);
    int acoff = (lane >> 4) << 3;
    int brow = wn + ((lane >> 4) << 3) + (lane & 7);
    int bcoff = lane & 8;

    float4 xa[8];
#define LOAD_A(t)                                                              \
    do {                                                                       \
        int base_ = (t) * 64;                                                  \
        _Pragma("unroll")                                                      \
        for (int j = 0; j < 8; j++) {                                          \
            int i_ = j * 256 + tid;                                            \
            int row_ = base_ + (i_ >> 5);                                      \
            int c4_ = (i_ & 31) << 2;                                          \
            xa[j] = (row_ < E)                                                 \
                ? __ldcs((const float4*)(angle + (size_t)row_ * HID + c4_))    \
                : make_float4(0.f, 0.f, 0.f, 0.f);                             \
        }                                                                      \
    } while (0)

#define STORE_A(buf)                                                           \
    do {                                                                       \
        char* Ab_ = sm + ((buf) ? ESM_A1 : ESM_A0);                            \
        _Pragma("unroll")                                                      \
        for (int j = 0; j < 8; j++) {                                          \
            int i_ = j * 256 + tid;                                            \
            int r_ = i_ >> 5;                                                  \
            int c4_ = (i_ & 31) << 2;                                          \
            uint32_t swo_ = swz64(r_, c4_);                                    \
            *(__half2*)(Ab_ + swo_)     = __floats2half2_rn(xa[j].x, xa[j].y); \
            *(__half2*)(Ab_ + swo_ + 4) = __floats2half2_rn(xa[j].z, xa[j].w); \
        }                                                                      \
    } while (0)

    int tile0 = blockIdx.x;
    int stride = gridDim.x;
    if (tile0 >= numTiles) return;

    LOAD_A(tile0);
    STORE_A(0);
    __syncthreads();

    int buf = 0;
#pragma unroll 1
    for (int t = tile0; t < numTiles; t += stride) {
        int tn = t + stride;
        if (tn < numTiles) LOAD_A(tn);

        float acc[2][4][4];
#pragma unroll
        for (int mi = 0; mi < 2; mi++)
#pragma unroll
            for (int nj = 0; nj < 4; nj++)
#pragma unroll
                for (int tt = 0; tt < 4; tt++) acc[mi][nj][tt] = 0.f;

        uint32_t abase = smb + (buf ? ESM_A1 : ESM_A0);
#pragma unroll
        for (int ks = 0; ks < 8; ks++) {
            int k0 = ks * 16;
            uint32_t ahi[2][4];
            ldsm4(ahi[0], abase + swz64(arow, k0 + acoff));
            ldsm4(ahi[1], abase + swz64(arow + 16, k0 + acoff));
            uint32_t bhi[2][4], blo[2][4];
#pragma unroll
            for (int p = 0; p < 2; p++) {
                uint32_t boff = swz(brow + p * 16, k0 + bcoff);
                ldsm4(bhi[p], smb + SM_BH + boff);
                ldsm4(blo[p], smb + SM_BL + boff);
            }
#pragma unroll
            for (int mi = 0; mi < 2; mi++) {
#pragma unroll
                for (int nj = 0; nj < 4; nj++) {
                    int p = nj >> 1, hh = (nj & 1) * 2;
                    mma_f16(acc[mi][nj], ahi[mi], bhi[p][hh], bhi[p][hh + 1]);
                    mma_f16(acc[mi][nj], ahi[mi], blo[p][hh], blo[p][hh + 1]);
                }
            }
        }

        int r0 = t * 64 + wm + (lane >> 2);
        int cbase = wn + (lane & 3) * 2;
#pragma unroll
        for (int mi = 0; mi < 2; mi++) {
            int ra = r0 + mi * 16;
            int rb = ra + 8;
#pragma unroll
            for (int nj = 0; nj < 4; nj++) {
                int c = cbase + nj * 8;
                if (ra < E) {
                    __half2 h = __floats2half2_rn(acc[mi][nj][0], acc[mi][nj][1]);
                    uint32_t u = *(uint32_t*)&h;
                    asm volatile("st.global.cs.u32 [%0], %1;"
                                 :: "l"(g_eh + (size_t)ra * HID + c), "r"(u) : "memory");
                }
                if (rb < E) {
                    __half2 h = __floats2half2_rn(acc[mi][nj][2], acc[mi][nj][3]);
                    uint32_t u = *(uint32_t*)&h;
                    asm volatile("st.global.cs.u32 [%0], %1;"
                                 :: "l"(g_eh + (size_t)rb * HID + c), "r"(u) : "memory");
                }
            }
        }

        if (tn < numTiles) STORE_A(buf ^ 1);
        __syncthreads();
        buf ^= 1;
    }
#undef LOAD_A
#undef STORE_A
}

// ---------------- attention gather v4: se software-pipelined, 4-edge, fp16 ----------------
__global__ __launch_bounds__(256) void attn_gather_kernel(int N)
{
    int warp = threadIdx.x >> 5;
    int lane = threadIdx.x & 31;
    int n = blockIdx.x * 8 + warp;
    if (n >= N) return;
    int c = lane * 4;

    float4 q4 = *(const float4*)(g_q + (size_t)n * HID + c);
    float4 acc = make_float4(0.f, 0.f, 0.f, 0.f);
    float zacc = 0.f;

    int beg = g_off[n], end = g_off[n + 1];
    int i = beg;

    // prefetch first 4 se entries
    int2 sse[4];
#pragma unroll
    for (int j = 0; j < 4; j++)
        sse[j] = (i + j < end) ? g_se[i + j] : make_int2(0, 0);

#pragma unroll 1
    for (; i + 4 <= end; i += 4) {
        // prefetch NEXT iteration's indices (overlaps with this iteration's work)
        int2 nse[4];
#pragma unroll
        for (int j = 0; j < 4; j++) {
            int t = i + 4 + j;
            nse[j] = (t < end) ? g_se[t] : make_int2(0, 0);
        }

        // gathers: addresses already known, issue immediately
        uint2 eu0 = __ldcs((const uint2*)(g_eh + (size_t)sse[0].y * HID + c));
        uint2 eu1 = __ldcs((const uint2*)(g_eh + (size_t)sse[1].y * HID + c));
        uint2 eu2 = __ldcs((const uint2*)(g_eh + (size_t)sse[2].y * HID + c));
        uint2 eu3 = __ldcs((const uint2*)(g_eh + (size_t)sse[3].y * HID + c));
        uint2 ku0 = *(const uint2*)(g_kh + (size_t)sse[0].x * HID + c);
        uint2 ku1 = *(const uint2*)(g_kh + (size_t)sse[1].x * HID + c);
        uint2 ku2 = *(const uint2*)(g_kh + (size_t)sse[2].x * HID + c);
        uint2 ku3 = *(const uint2*)(g_kh + (size_t)sse[3].x * HID + c);
        uint2 vu0 = *(const uint2*)(g_vh + (size_t)sse[0].x * HID + c);
        uint2 vu1 = *(const uint2*)(g_vh + (size_t)sse[1].x * HID + c);
        uint2 vu2 = *(const uint2*)(g_vh + (size_t)sse[2].x * HID + c);
        uint2 vu3 = *(const uint2*)(g_vh + (size_t)sse[3].x * HID + c);

        float2 ea0 = __half22float2(*(__half2*)&eu0.x), eb0 = __half22float2(*(__half2*)&eu0.y);
        float2 ea1 = __half22float2(*(__half2*)&eu1.x), eb1 = __half22float2(*(__half2*)&eu1.y);
        float2 ea2 = __half22float2(*(__half2*)&eu2.x), eb2 = __half22float2(*(__half2*)&eu2.y);
        float2 ea3 = __half22float2(*(__half2*)&eu3.x), eb3 = __half22float2(*(__half2*)&eu3.y);
        float2 ka0 = __half22float2(*(__half2*)&ku0.x), kb0 = __half22float2(*(__half2*)&ku0.y);
        float2 ka1 = __half22float2(*(__half2*)&ku1.x), kb1 = __half22float2(*(__half2*)&ku1.y);
        float2 ka2 = __half22float2(*(__half2*)&ku2.x), kb2 = __half22float2(*(__half2*)&ku2.y);
        float2 ka3 = __half22float2(*(__half2*)&ku3.x), kb3 = __half22float2(*(__half2*)&ku3.y);

        float p0 = q4.x * (ka0.x + ea0.x) + q4.y * (ka0.y + ea0.y)
                 + q4.z * (kb0.x + eb0.x) + q4.w * (kb0.y + eb0.y);
        float p1 = q4.x * (ka1.x + ea1.x) + q4.y * (ka1.y + ea1.y)
                 + q4.z * (kb1.x + eb1.x) + q4.w * (kb1.y + eb1.y);
        float p2 = q4.x * (ka2.x + ea2.x) + q4.y * (ka2.y + ea2.y)
                 + q4.z * (kb2.x + eb2.x) + q4.w * (kb2.y + eb2.y);
        float p3 = q4.x * (ka3.x + ea3.x) + q4.y * (ka3.y + ea3.y)
                 + q4.z * (kb3.x + eb3.x) + q4.w * (kb3.y + eb3.y);
        p0 += __shfl_xor_sync(0xffffffffu, p0, 1);
        p1 += __shfl_xor_sync(0xffffffffu, p1, 1);
        p2 += __shfl_xor_sync(0xffffffffu, p2, 1);
        p3 += __shfl_xor_sync(0xffffffffu, p3, 1);
        p0 += __shfl_xor_sync(0xffffffffu, p0, 2);
        p1 += __shfl_xor_sync(0xffffffffu, p1, 2);
        p2 += __shfl_xor_sync(0xffffffffu, p2, 2);
        p3 += __shfl_xor_sync(0xffffffffu, p3, 2);
        float a0 = __expf(p0 * 0.25f);   // /sqrt(16); alpha bounded, no max-shift needed
        float a1 = __expf(p1 * 0.25f);
        float a2 = __expf(p2 * 0.25f);
        float a3 = __expf(p3 * 0.25f);
        zacc += (a0 + a1) + (a2 + a3);

        float2 va0 = __half22float2(*(__half2*)&vu0.x), vb0 = __half22float2(*(__half2*)&vu0.y);
        float2 va1 = __half22float2(*(__half2*)&vu1.x), vb1 = __half22float2(*(__half2*)&vu1.y);
        float2 va2 = __half22float2(*(__half2*)&vu2.x), vb2 = __half22float2(*(__half2*)&vu2.y);
        float2 va3 = __half22float2(*(__half2*)&vu3.x), vb3 = __half22float2(*(__half2*)&vu3.y);
        acc.x += a0 * (va0.x + ea0.x) + a1 * (va1.x + ea1.x)
               + a2 * (va2.x + ea2.x) + a3 * (va3.x + ea3.x);
        acc.y += a0 * (va0.y + ea0.y) + a1 * (va1.y + ea1.y)
               + a2 * (va2.y + ea2.y) + a3 * (va3.y + ea3.y);
        acc.z += a0 * (vb0.x + eb0.x) + a1 * (vb1.x + eb1.x)
               + a2 * (vb2.x + eb2.x) + a3 * (vb3.x + eb3.x);
        acc.w += a0 * (vb0.y + eb0.y) + a1 * (vb1.y + eb1.y)
               + a2 * (vb2.y + eb2.y) + a3 * (vb3.y + eb3.y);

#pragma unroll
        for (int j = 0; j < 4; j++) sse[j] = nse[j];
    }
    // tail (0-3 edges), uses prefetched sse
#pragma unroll 1
    for (int j = 0; i < end; i++, j++) {
        int2 se = sse[j];
        uint2 eu = __ldcs((const uint2*)(g_eh + (size_t)se.y * HID + c));
        uint2 ku = *(const uint2*)(g_kh + (size_t)se.x * HID + c);
        uint2 vu = *(const uint2*)(g_vh + (size_t)se.x * HID + c);
        float2 ea = __half22float2(*(__half2*)&eu.x);
        float2 eb = __half22float2(*(__half2*)&eu.y);
        float2 ka = __half22float2(*(__half2*)&ku.x);
        float2 kb = __half22float2(*(__half2*)&ku.y);
        float p = q4.x * (ka.x + ea.x) + q4.y * (ka.y + ea.y)
                + q4.z * (kb.x + eb.x) + q4.w * (kb.y + eb.y);
        p += __shfl_xor_sync(0xffffffffu, p, 1);
        p += __shfl_xor_sync(0xffffffffu, p, 2);
        float a = __expf(p * 0.25f);
        zacc += a;
        float2 va = __half22float2(*(__half2*)&vu.x);
        float2 vb = __half22float2(*(__half2*)&vu.y);
        acc.x += a * (va.x + ea.x);
        acc.y += a * (va.y + ea.y);
        acc.z += a * (vb.x + eb.x);
        acc.w += a * (vb.y + eb.y);
    }

    *(float4*)(g_num + (size_t)n * HID + c) = acc;
    if ((lane & 3) == 0) g_z[(size_t)n * NHEAD + (lane >> 2)] = zacc;
}

// ---------------- finalize ----------------
__global__ __launch_bounds__(256) void finalize_kernel(
    const float* __restrict__ x, const float* __restrict__ Wbeta,
    const float* __restrict__ gamma, const float* __restrict__ lbeta,
    float* __restrict__ out, int N)
{
    int warp = threadIdx.x >> 5;
    int lane = threadIdx.x & 31;
    int n = blockIdx.x * 8 + warp;
    if (n >= N) return;
    int c = lane * 4;

    float4 num = *(const float4*)(g_num + (size_t)n * HID + c);
    float z = g_z[(size_t)n * NHEAD + (lane >> 2)];
    float inv = z > 0.f ? 1.f / z : 0.f;
    float4 o = make_float4(num.x * inv, num.y * inv, num.z * inv, num.w * inv);
    float4 xr = *(const float4*)(g_xr + (size_t)n * HID + c);

    float4 wb0 = *(const float4*)(Wbeta + c);
    float4 wb1 = *(const float4*)(Wbeta + 128 + c);
    float4 wb2 = *(const float4*)(Wbeta + 256 + c);
    float dot = o.x * wb0.x + o.y * wb0.y + o.z * wb0.z + o.w * wb0.w
              + xr.x * wb1.x + xr.y * wb1.y + xr.z * wb1.z + xr.w * wb1.w
              + (o.x - xr.x) * wb2.x + (o.y - xr.y) * wb2.y
              + (o.z - xr.z) * wb2.z + (o.w - xr.w) * wb2.w;
#pragma unroll
    for (int m = 16; m; m >>= 1) dot += __shfl_xor_sync(0xffffffffu, dot, m);
    float beta = 1.f / (1.f + __expf(-dot));

    float4 g;
    g.x = beta * xr.x + (1.f - beta) * o.x;
    g.y = beta * xr.y + (1.f - beta) * o.y;
    g.z = beta * xr.z + (1.f - beta) * o.z;
    g.w = beta * xr.w + (1.f - beta) * o.w;

    float sgm = g.x + g.y + g.z + g.w;
#pragma unroll
    for (int m = 16; m; m >>= 1) sgm += __shfl_xor_sync(0xffffffffu, sgm, m);
    float mu = sgm * (1.f / 128.f);

    float dx = g.x - mu, dy = g.y - mu, dz = g.z - mu, dw = g.w - mu;
    float vs = dx * dx + dy * dy + dz * dz + dw * dw;
#pragma unroll
    for (int m = 16; m; m >>= 1) vs += __shfl_xor_sync(0xffffffffu, vs, m);
    float rstd = rsqrtf(vs * (1.f / 128.f) + 1e-5f);

    float4 gm = *(const float4*)(gamma + c);
    float4 lb = *(const float4*)(lbeta + c);
    float4 xin = *(const float4*)(x + (size_t)n * HID + c);

    float4 res;
    float y;
    y = dx * rstd * gm.x + lb.x; res.x = xin.x + fmaxf(y, 0.f);
    y = dy * rstd * gm.y + lb.y; res.y = xin.y + fmaxf(y, 0.f);
    y = dz * rstd * gm.z + lb.z; res.z = xin.z + fmaxf(y, 0.f);
    y = dw * rstd * gm.w + lb.w; res.w = xin.w + fmaxf(y, 0.f);
    *(float4*)(out + (size_t)n * HID + c) = res;
}

// ---------------- launch ----------------
extern "C" void kernel_launch(void* const* d_in, const int* in_sizes, int n_in,
                              void* d_out, int out_size)
{
    const float* edge_state = (const float*)d_in[0];
    const void*  idx        = d_in[1];
    const float* angle      = (const float*)d_in[2];
    const float* Wq = (const float*)d_in[3];
    const float* bq = (const float*)d_in[4];
    const float* Wk = (const float*)d_in[5];
    const float* bk = (const float*)d_in[6];
    const float* Wv = (const float*)d_in[7];
    const float* bv = (const float*)d_in[8];
    const float* We = (const float*)d_in[9];
    const float* Ws = (const float*)d_in[10];
    const float* bs = (const float*)d_in[11];
    const float* Wbeta = (const float*)d_in[12];
    const float* gamma = (const float*)d_in[13];
    const float* lbeta = (const float*)d_in[14];

    int N = in_sizes[0] / HID;
    int E = in_sizes[2] / HID;
    int numTiles = (E + 63) / 64;
    int egrid = 296;                 // 2 persistent CTAs per SM
    if (egrid > numTiles) egrid = numTiles;

    cudaFuncSetAttribute(node_hmma_kernel, cudaFuncAttributeMaxDynamicSharedMemorySize, SM_TOTAL);
    cudaFuncSetAttribute(egemm_pipe_kernel, cudaFuncAttributeMaxDynamicSharedMemorySize, ESM_TOTAL);

    // launch order: egemm is the 4th launch so the ncu capture slot lands on it
    detect_kernel<<<1, 32>>>(idx, (long long)in_sizes[1]);
    prep_w_kernel<<<5, 128>>>(Wq, Wk, Wv, Ws, We);
    zero_deg_kernel<<<(N + 255) / 256, 256>>>(N);

    egemm_pipe_kernel<<<egrid, 256, ESM_TOTAL>>>(angle, E, numTiles);   // 4th

    count_kernel<<<(E + 255) / 256, 256>>>(idx, E);
    scan_kernel<<<1, 1024>>>(N, E);
    scatter_kernel<<<(E + 255) / 256, 256>>>(idx, E);

    node_hmma_kernel<<<(N + 127) / 128, 256, SM_TOTAL>>>(edge_state, bq, bk, bv, bs, N);

    attn_gather_kernel<<<(N + 7) / 8, 256>>>(N);

    finalize_kernel<<<(N + 7) / 8, 256>>>(edge_state, Wbeta, gamma, lbeta,
                                          (float*)d_out, N);
}

// round 17
// speedup vs baseline: 1.0702x; 1.0702x over previous
#include <cuda_runtime.h>
#include <cuda_fp16.h>
#include <cstdint>

#define HID 128
#define NHEAD 8
#define HD 16
#define MAXN 50000
#define MAXE 500000

typedef unsigned long long ull;

// ---------------- static device scratch ----------------
__device__ float g_q[MAXN * HID];
__device__ __half g_kh[MAXN * HID];           // k fp16 (only consumer: attn)
__device__ __half g_vh[MAXN * HID];           // v fp16
__device__ float g_xr[MAXN * HID];
__device__ float g_num[MAXN * HID];
__device__ float g_z[MAXN * NHEAD];
__device__ __half g_eh[(size_t)MAXE * HID];   // e rows fp16, edge-id order
__device__ int   g_is64;
// CSR by destination
__device__ int g_deg[MAXN];
__device__ int g_off[MAXN + 1];
__device__ int g_pos[MAXN];
__device__ int2 g_se[MAXE];                   // per CSR slot: {src node, edge id}
// 5 weights: hi/lo fp16 blobs, transposed B[n][k], 128x128 swizzled (32KB each)
__device__ __half g_wt[5][2][128 * 128];

// ---------------- helpers ----------------
__device__ __forceinline__ uint32_t smem_u32(const void* p) {
    uint32_t a;
    asm("{ .reg .u64 t; cvta.to.shared.u64 t, %1; cvt.u32.u64 %0, t; }" : "=r"(a) : "l"(p));
    return a;
}

// [128 rows x 128 k] fp16 tile: two 64-k blocks of 16KB, 128B rows, XOR swizzle
__device__ __forceinline__ uint32_t swz(int row, int k) {
    uint32_t off = ((uint32_t)(k >> 6) << 14) + ((uint32_t)row << 7) + ((uint32_t)(k & 63) << 1);
    return off ^ ((off >> 3) & 0x70);
}
// [64 rows x 128 k] fp16 tile: two 64-k blocks of 8KB
__device__ __forceinline__ uint32_t swz64(int row, int k) {
    uint32_t off = ((uint32_t)(k >> 6) << 13) + ((uint32_t)row << 7) + ((uint32_t)(k & 63) << 1);
    return off ^ ((off >> 3) & 0x70);
}

__device__ __forceinline__ void ldsm4(uint32_t* r, uint32_t addr) {
    asm volatile("ldmatrix.sync.aligned.m8n8.x4.shared.b16 {%0,%1,%2,%3}, [%4];"
                 : "=r"(r[0]), "=r"(r[1]), "=r"(r[2]), "=r"(r[3]) : "r"(addr));
}

__device__ __forceinline__ void mma_f16(float* d, const uint32_t* a, uint32_t b0, uint32_t b1) {
    asm("mma.sync.aligned.m16n8k16.row.col.f32.f16.f16.f32 "
        "{%0,%1,%2,%3}, {%4,%5,%6,%7}, {%8,%9}, {%0,%1,%2,%3};"
        : "+f"(d[0]), "+f"(d[1]), "+f"(d[2]), "+f"(d[3])
        : "r"(a[0]), "r"(a[1]), "r"(a[2]), "r"(a[3]), "r"(b0), "r"(b1));
}

// pipe smem layout (both GEMM kernels): A0 16KB | A1 16KB | B-hi 32KB | B-lo 32KB
#define ESM_A0 0
#define ESM_A1 16384
#define SM_BH  32768
#define SM_BL  65536
#define ESM_TOTAL 98304

// ---------------- small kernels ----------------
__global__ void detect_kernel(const void* idx, long long total_elems) {
    if (threadIdx.x == 0 && blockIdx.x == 0) {
        const long long* p = (const long long*)idx;
        long long n = total_elems / 2;
        if (n > 256) n = 256;
        int is64 = 1;
        for (long long i = 0; i < n; i++) {
            long long v = p[i];
            if (v < 0 || v >= (1LL << 31)) is64 = 0;
        }
        g_is64 = is64;
    }
}

__global__ void zero_deg_kernel(int N) {
    int i = blockIdx.x * blockDim.x + threadIdx.x;
    if (i < N) g_deg[i] = 0;
}

__global__ void count_kernel(const void* __restrict__ idx, int E) {
    int e = blockIdx.x * 256 + threadIdx.x;
    if (e >= E) return;
    int d;
    if (g_is64) d = (int)((const long long*)idx)[e + E];
    else        d = ((const int*)idx)[e + E];
    atomicAdd(&g_deg[d], 1);
}

// single-block exclusive scan over g_deg -> g_off, g_pos
__global__ void scan_kernel(int N, int E) {
    __shared__ int sums[1024];
    int t = threadIdx.x;
    int C = (N + 1023) / 1024;
    int b = t * C;
    int hi = b + C; if (hi > N) hi = N;
    int s = 0;
    for (int i = b; i < hi; i++) s += g_deg[i];
    sums[t] = s;
    __syncthreads();
    for (int ofs = 1; ofs < 1024; ofs <<= 1) {
        int v = (t >= ofs) ? sums[t - ofs] : 0;
        __syncthreads();
        sums[t] += v;
        __syncthreads();
    }
    int run = (t == 0) ? 0 : sums[t - 1];
    for (int i = b; i < hi; i++) {
        g_off[i] = run;
        g_pos[i] = run;
        run += g_deg[i];
    }
    if (t == 1023) g_off[N] = E;
}

__global__ void scatter_kernel(const void* __restrict__ idx, int E) {
    int e = blockIdx.x * 256 + threadIdx.x;
    if (e >= E) return;
    int s, d;
    if (g_is64) {
        const long long* p = (const long long*)idx;
        s = (int)p[e]; d = (int)p[e + E];
    } else {
        const int* p = (const int*)idx;
        s = p[e]; d = p[e + E];
    }
    int p = atomicAdd(&g_pos[d], 1);
    g_se[p] = make_int2(s, e);
}

// W ([in=128,out=128] row-major) -> B[n][k]=W[k][n]; fp16 hi/lo; swizzled 128x128 blobs
__global__ void prep_w_kernel(const float* W0, const float* W1, const float* W2,
                              const float* W3, const float* W4) {
    const float* W = W0;
    if (blockIdx.x == 1) W = W1;
    else if (blockIdx.x == 2) W = W2;
    else if (blockIdx.x == 3) W = W3;
    else if (blockIdx.x == 4) W = W4;
    char* hi = (char*)g_wt[blockIdx.x][0];
    char* lo = (char*)g_wt[blockIdx.x][1];
    for (int i = threadIdx.x; i < 128 * 128; i += blockDim.x) {
        int n = i & 127, k = i >> 7;
        float x = W[k * 128 + n];               // coalesced over n
        __half hv = __float2half(x);
        __half lv = __float2half(x - __half2float(hv));
        uint32_t sw = swz(n, k);
        *(__half*)(hi + sw) = hv;
        *(__half*)(lo + sw) = lv;
    }
}

__device__ __forceinline__ void stage_B(int wi, char* sm, int tid)
{
    const float4* sH = (const float4*)g_wt[wi][0];
    const float4* sL = (const float4*)g_wt[wi][1];
    float4* dH = (float4*)(sm + SM_BH);
    float4* dL = (float4*)(sm + SM_BL);
    for (int i = tid; i < 2048; i += 256) { dH[i] = sH[i]; dL[i] = sL[i]; }
}

// -------- shared pipe macros: 64x128 A tile via 8 float4/thread --------
#define LOAD_AX(ptr, t, RMAX)                                                  \
    do {                                                                       \
        int base_ = (t) * 64;                                                  \
        _Pragma("unroll")                                                      \
        for (int j = 0; j < 8; j++) {                                          \
            int i_ = j * 256 + tid;                                            \
            int row_ = base_ + (i_ >> 5);                                      \
            int c4_ = (i_ & 31) << 2;                                          \
            xa[j] = (row_ < (RMAX))                                            \
                ? __ldcs((const float4*)((ptr) + (size_t)row_ * HID + c4_))    \
                : make_float4(0.f, 0.f, 0.f, 0.f);                             \
        }                                                                      \
    } while (0)

#define STORE_AX(buf)                                                          \
    do {                                                                       \
        char* Ab_ = sm + ((buf) ? ESM_A1 : ESM_A0);                            \
        _Pragma("unroll")                                                      \
        for (int j = 0; j < 8; j++) {                                          \
            int i_ = j * 256 + tid;                                            \
            int r_ = i_ >> 5;                                                  \
            int c4_ = (i_ & 31) << 2;                                          \
            uint32_t swo_ = swz64(r_, c4_);                                    \
            *(__half2*)(Ab_ + swo_)     = __floats2half2_rn(xa[j].x, xa[j].y); \
            *(__half2*)(Ab_ + swo_ + 4) = __floats2half2_rn(xa[j].z, xa[j].w); \
        }                                                                      \
    } while (0)

#define PIPE_MMA(buf, acc)                                                     \
    do {                                                                       \
        uint32_t abase_ = smb + ((buf) ? ESM_A1 : ESM_A0);                     \
        _Pragma("unroll")                                                      \
        for (int ks = 0; ks < 8; ks++) {                                       \
            int k0 = ks * 16;                                                  \
            uint32_t ahi[2][4];                                                \
            ldsm4(ahi[0], abase_ + swz64(arow, k0 + acoff));                   \
            ldsm4(ahi[1], abase_ + swz64(arow + 16, k0 + acoff));              \
            uint32_t bhi[2][4], blo[2][4];                                     \
            _Pragma("unroll")                                                  \
            for (int p = 0; p < 2; p++) {                                      \
                uint32_t boff = swz(brow + p * 16, k0 + bcoff);                \
                ldsm4(bhi[p], smb + SM_BH + boff);                             \
                ldsm4(blo[p], smb + SM_BL + boff);                             \
            }                                                                  \
            _Pragma("unroll")                                                  \
            for (int mi = 0; mi < 2; mi++) {                                   \
                _Pragma("unroll")                                              \
                for (int nj = 0; nj < 4; nj++) {                               \
                    int p = nj >> 1, hh = (nj & 1) * 2;                        \
                    mma_f16(acc[mi][nj], ahi[mi], bhi[p][hh], bhi[p][hh + 1]); \
                    mma_f16(acc[mi][nj], ahi[mi], blo[p][hh], blo[p][hh + 1]); \
                }                                                              \
            }                                                                  \
        }                                                                      \
    } while (0)

// ---------------- node pipe: persistent, 4 weights, double-buffered A ----------------
__global__ __launch_bounds__(256, 2) void node_pipe_kernel(
    const float* __restrict__ X,
    const float* __restrict__ bq, const float* __restrict__ bk,
    const float* __restrict__ bv, const float* __restrict__ bs,
    int M, int numTiles)
{
    extern __shared__ char sm[];
    uint32_t smb = smem_u32(sm);
    int tid = threadIdx.x;
    int lane = tid & 31, w = tid >> 5;
    int wm = (w >> 2) * 32, wn = (w & 3) * 32;

    int arow = wm + (lane & 15);
    int acoff = (lane >> 4) << 3;
    int brow = wn + ((lane >> 4) << 3) + (lane & 7);
    int bcoff = lane & 8;

    int tile0 = blockIdx.x;
    int stride = gridDim.x;
    if (tile0 >= numTiles) return;

    const float* biases[4] = {bq, bk, bv, bs};
    float4 xa[8];

#pragma unroll 1
    for (int wi = 0; wi < 4; wi++) {
        __syncthreads();                 // previous weight's B reads finished
        stage_B(wi, sm, tid);
        LOAD_AX(X, tile0, M);
        STORE_AX(0);
        __syncthreads();                 // B + A0 staged

        // per-thread bias values (columns fixed per thread)
        const float* bias = biases[wi];
        int cbase = wn + (lane & 3) * 2;
        float bv0[4], bv1[4];
#pragma unroll
        for (int nj = 0; nj < 4; nj++) {
            bv0[nj] = __ldg(bias + cbase + nj * 8);
            bv1[nj] = __ldg(bias + cbase + nj * 8 + 1);
        }
        bool isf16 = (wi == 1 || wi == 2);
        float* outf = (wi == 0) ? g_q : g_xr;
        __half* outh = (wi == 1) ? g_kh : g_vh;

        int buf = 0;
#pragma unroll 1
        for (int t = tile0; t < numTiles; t += stride) {
            int tn = t + stride;
            if (tn < numTiles) LOAD_AX(X, tn, M);

            float acc[2][4][4];
#pragma unroll
            for (int mi = 0; mi < 2; mi++)
#pragma unroll
                for (int nj = 0; nj < 4; nj++)
#pragma unroll
                    for (int tt = 0; tt < 4; tt++) acc[mi][nj][tt] = 0.f;

            PIPE_MMA(buf, acc);

            int r0 = t * 64 + wm + (lane >> 2);
#pragma unroll
            for (int mi = 0; mi < 2; mi++) {
                int ra = r0 + mi * 16;
                int rb = ra + 8;
#pragma unroll
                for (int nj = 0; nj < 4; nj++) {
                    int cc = cbase + nj * 8;
                    float xa0 = acc[mi][nj][0] + bv0[nj], xa1 = acc[mi][nj][1] + bv1[nj];
                    float xb0 = acc[mi][nj][2] + bv0[nj], xb1 = acc[mi][nj][3] + bv1[nj];
                    if (isf16) {
                        if (ra < M) *(__half2*)(outh + (size_t)ra * HID + cc) = __floats2half2_rn(xa0, xa1);
                        if (rb < M) *(__half2*)(outh + (size_t)rb * HID + cc) = __floats2half2_rn(xb0, xb1);
                    } else {
                        if (ra < M) *(float2*)(outf + (size_t)ra * HID + cc) = make_float2(xa0, xa1);
                        if (rb < M) *(float2*)(outf + (size_t)rb * HID + cc) = make_float2(xb0, xb1);
                    }
                }
            }

            if (tn < numTiles) STORE_AX(buf ^ 1);
            __syncthreads();
            buf ^= 1;
        }
    }
}

// ---------------- egemm pipe: persistent, double-buffered 64-row tiles ----------------
__global__ __launch_bounds__(256, 2) void egemm_pipe_kernel(
    const float* __restrict__ angle, int E, int numTiles)
{
    extern __shared__ char sm[];
    uint32_t smb = smem_u32(sm);
    int tid = threadIdx.x;
    int lane = tid & 31, w = tid >> 5;
    int wm = (w >> 2) * 32, wn = (w & 3) * 32;

    stage_B(4, sm, tid);    // B resident for the whole kernel

    int arow = wm + (lane & 15);
    int acoff = (lane >> 4) << 3;
    int brow = wn + ((lane >> 4) << 3) + (lane & 7);
    int bcoff = lane & 8;

    int tile0 = blockIdx.x;
    int stride = gridDim.x;
    if (tile0 >= numTiles) return;

    float4 xa[8];
    LOAD_AX(angle, tile0, E);
    STORE_AX(0);
    __syncthreads();

    int buf = 0;
#pragma unroll 1
    for (int t = tile0; t < numTiles; t += stride) {
        int tn = t + stride;
        if (tn < numTiles) LOAD_AX(angle, tn, E);

        float acc[2][4][4];
#pragma unroll
        for (int mi = 0; mi < 2; mi++)
#pragma unroll
            for (int nj = 0; nj < 4; nj++)
#pragma unroll
                for (int tt = 0; tt < 4; tt++) acc[mi][nj][tt] = 0.f;

        PIPE_MMA(buf, acc);

        int r0 = t * 64 + wm + (lane >> 2);
        int cbase = wn + (lane & 3) * 2;
#pragma unroll
        for (int mi = 0; mi < 2; mi++) {
            int ra = r0 + mi * 16;
            int rb = ra + 8;
#pragma unroll
            for (int nj = 0; nj < 4; nj++) {
                int c = cbase + nj * 8;
                if (ra < E) {
                    __half2 h = __floats2half2_rn(acc[mi][nj][0], acc[mi][nj][1]);
                    uint32_t u = *(uint32_t*)&h;
                    asm volatile("st.global.cs.u32 [%0], %1;"
                                 :: "l"(g_eh + (size_t)ra * HID + c), "r"(u) : "memory");
                }
                if (rb < E) {
                    __half2 h = __floats2half2_rn(acc[mi][nj][2], acc[mi][nj][3]);
                    uint32_t u = *(uint32_t*)&h;
                    asm volatile("st.global.cs.u32 [%0], %1;"
                                 :: "l"(g_eh + (size_t)rb * HID + c), "r"(u) : "memory");
                }
            }
        }

        if (tn < numTiles) STORE_AX(buf ^ 1);
        __syncthreads();
        buf ^= 1;
    }
}

// ---------------- attention gather (round-15 form): warp/node, 4-edge, fp16 ----------------
__global__ __launch_bounds__(256) void attn_gather_kernel(int N)
{
    int warp = threadIdx.x >> 5;
    int lane = threadIdx.x & 31;
    int n = blockIdx.x * 8 + warp;
    if (n >= N) return;
    int c = lane * 4;

    float4 q4 = *(const float4*)(g_q + (size_t)n * HID + c);
    float4 acc = make_float4(0.f, 0.f, 0.f, 0.f);
    float zacc = 0.f;

    int beg = g_off[n], end = g_off[n + 1];
    int i = beg;

#pragma unroll 1
    for (; i + 4 <= end; i += 4) {
        int2 se0 = g_se[i];
        int2 se1 = g_se[i + 1];
        int2 se2 = g_se[i + 2];
        int2 se3 = g_se[i + 3];
        uint2 eu0 = __ldcs((const uint2*)(g_eh + (size_t)se0.y * HID + c));
        uint2 eu1 = __ldcs((const uint2*)(g_eh + (size_t)se1.y * HID + c));
        uint2 eu2 = __ldcs((const uint2*)(g_eh + (size_t)se2.y * HID + c));
        uint2 eu3 = __ldcs((const uint2*)(g_eh + (size_t)se3.y * HID + c));
        uint2 ku0 = *(const uint2*)(g_kh + (size_t)se0.x * HID + c);
        uint2 ku1 = *(const uint2*)(g_kh + (size_t)se1.x * HID + c);
        uint2 ku2 = *(const uint2*)(g_kh + (size_t)se2.x * HID + c);
        uint2 ku3 = *(const uint2*)(g_kh + (size_t)se3.x * HID + c);
        uint2 vu0 = *(const uint2*)(g_vh + (size_t)se0.x * HID + c);
        uint2 vu1 = *(const uint2*)(g_vh + (size_t)se1.x * HID + c);
        uint2 vu2 = *(const uint2*)(g_vh + (size_t)se2.x * HID + c);
        uint2 vu3 = *(const uint2*)(g_vh + (size_t)se3.x * HID + c);

        float2 ea0 = __half22float2(*(__half2*)&eu0.x), eb0 = __half22float2(*(__half2*)&eu0.y);
        float2 ea1 = __half22float2(*(__half2*)&eu1.x), eb1 = __half22float2(*(__half2*)&eu1.y);
        float2 ea2 = __half22float2(*(__half2*)&eu2.x), eb2 = __half22float2(*(__half2*)&eu2.y);
        float2 ea3 = __half22float2(*(__half2*)&eu3.x), eb3 = __half22float2(*(__half2*)&eu3.y);
        float2 ka0 = __half22float2(*(__half2*)&ku0.x), kb0 = __half22float2(*(__half2*)&ku0.y);
        float2 ka1 = __half22float2(*(__half2*)&ku1.x), kb1 = __half22float2(*(__half2*)&ku1.y);
        float2 ka2 = __half22float2(*(__half2*)&ku2.x), kb2 = __half22float2(*(__half2*)&ku2.y);
        float2 ka3 = __half22float2(*(__half2*)&ku3.x), kb3 = __half22float2(*(__half2*)&ku3.y);

        float p0 = q4.x * (ka0.x + ea0.x) + q4.y * (ka0.y + ea0.y)
                 + q4.z * (kb0.x + eb0.x) + q4.w * (kb0.y + eb0.y);
        float p1 = q4.x * (ka1.x + ea1.x) + q4.y * (ka1.y + ea1.y)
                 + q4.z * (kb1.x + eb1.x) + q4.w * (kb1.y + eb1.y);
        float p2 = q4.x * (ka2.x + ea2.x) + q4.y * (ka2.y + ea2.y)
                 + q4.z * (kb2.x + eb2.x) + q4.w * (kb2.y + eb2.y);
        float p3 = q4.x * (ka3.x + ea3.x) + q4.y * (ka3.y + ea3.y)
                 + q4.z * (kb3.x + eb3.x) + q4.w * (kb3.y + eb3.y);
        p0 += __shfl_xor_sync(0xffffffffu, p0, 1);
        p1 += __shfl_xor_sync(0xffffffffu, p1, 1);
        p2 += __shfl_xor_sync(0xffffffffu, p2, 1);
        p3 += __shfl_xor_sync(0xffffffffu, p3, 1);
        p0 += __shfl_xor_sync(0xffffffffu, p0, 2);
        p1 += __shfl_xor_sync(0xffffffffu, p1, 2);
        p2 += __shfl_xor_sync(0xffffffffu, p2, 2);
        p3 += __shfl_xor_sync(0xffffffffu, p3, 2);
        float a0 = __expf(p0 * 0.25f);   // /sqrt(16); alpha bounded, no max-shift needed
        float a1 = __expf(p1 * 0.25f);
        float a2 = __expf(p2 * 0.25f);
        float a3 = __expf(p3 * 0.25f);
        zacc += (a0 + a1) + (a2 + a3);

        float2 va0 = __half22float2(*(__half2*)&vu0.x), vb0 = __half22float2(*(__half2*)&vu0.y);
        float2 va1 = __half22float2(*(__half2*)&vu1.x), vb1 = __half22float2(*(__half2*)&vu1.y);
        float2 va2 = __half22float2(*(__half2*)&vu2.x), vb2 = __half22float2(*(__half2*)&vu2.y);
        float2 va3 = __half22float2(*(__half2*)&vu3.x), vb3 = __half22float2(*(__half2*)&vu3.y);
        acc.x += a0 * (va0.x + ea0.x) + a1 * (va1.x + ea1.x)
               + a2 * (va2.x + ea2.x) + a3 * (va3.x + ea3.x);
        acc.y += a0 * (va0.y + ea0.y) + a1 * (va1.y + ea1.y)
               + a2 * (va2.y + ea2.y) + a3 * (va3.y + ea3.y);
        acc.z += a0 * (vb0.x + eb0.x) + a1 * (vb1.x + eb1.x)
               + a2 * (vb2.x + eb2.x) + a3 * (vb3.x + eb3.x);
        acc.w += a0 * (vb0.y + eb0.y) + a1 * (vb1.y + eb1.y)
               + a2 * (vb2.y + eb2.y) + a3 * (vb3.y + eb3.y);
    }
#pragma unroll 1
    for (; i < end; i++) {
        int2 se = g_se[i];
        uint2 eu = __ldcs((const uint2*)(g_eh + (size_t)se.y * HID + c));
        uint2 ku = *(const uint2*)(g_kh + (size_t)se.x * HID + c);
        uint2 vu = *(const uint2*)(g_vh + (size_t)se.x * HID + c);
        float2 ea = __half22float2(*(__half2*)&eu.x);
        float2 eb = __half22float2(*(__half2*)&eu.y);
        float2 ka = __half22float2(*(__half2*)&ku.x);
        float2 kb = __half22float2(*(__half2*)&ku.y);
        float p = q4.x * (ka.x + ea.x) + q4.y * (ka.y + ea.y)
                + q4.z * (kb.x + eb.x) + q4.w * (kb.y + eb.y);
        p += __shfl_xor_sync(0xffffffffu, p, 1);
        p += __shfl_xor_sync(0xffffffffu, p, 2);
        float a = __expf(p * 0.25f);
        zacc += a;
        float2 va = __half22float2(*(__half2*)&vu.x);
        float2 vb = __half22float2(*(__half2*)&vu.y);
        acc.x += a * (va.x + ea.x);
        acc.y += a * (va.y + ea.y);
        acc.z += a * (vb.x + eb.x);
        acc.w += a * (vb.y + eb.y);
    }

    *(float4*)(g_num + (size_t)n * HID + c) = acc;
    if ((lane & 3) == 0) g_z[(size_t)n * NHEAD + (lane >> 2)] = zacc;
}

// ---------------- finalize ----------------
__global__ __launch_bounds__(256) void finalize_kernel(
    const float* __restrict__ x, const float* __restrict__ Wbeta,
    const float* __restrict__ gamma, const float* __restrict__ lbeta,
    float* __restrict__ out, int N)
{
    int warp = threadIdx.x >> 5;
    int lane = threadIdx.x & 31;
    int n = blockIdx.x * 8 + warp;
    if (n >= N) return;
    int c = lane * 4;

    float4 num = *(const float4*)(g_num + (size_t)n * HID + c);
    float z = g_z[(size_t)n * NHEAD + (lane >> 2)];
    float inv = z > 0.f ? 1.f / z : 0.f;
    float4 o = make_float4(num.x * inv, num.y * inv, num.z * inv, num.w * inv);
    float4 xr = *(const float4*)(g_xr + (size_t)n * HID + c);

    float4 wb0 = *(const float4*)(Wbeta + c);
    float4 wb1 = *(const float4*)(Wbeta + 128 + c);
    float4 wb2 = *(const float4*)(Wbeta + 256 + c);
    float dot = o.x * wb0.x + o.y * wb0.y + o.z * wb0.z + o.w * wb0.w
              + xr.x * wb1.x + xr.y * wb1.y + xr.z * wb1.z + xr.w * wb1.w
              + (o.x - xr.x) * wb2.x + (o.y - xr.y) * wb2.y
              + (o.z - xr.z) * wb2.z + (o.w - xr.w) * wb2.w;
#pragma unroll
    for (int m = 16; m; m >>= 1) dot += __shfl_xor_sync(0xffffffffu, dot, m);
    float beta = 1.f / (1.f + __expf(-dot));

    float4 g;
    g.x = beta * xr.x + (1.f - beta) * o.x;
    g.y = beta * xr.y + (1.f - beta) * o.y;
    g.z = beta * xr.z + (1.f - beta) * o.z;
    g.w = beta * xr.w + (1.f - beta) * o.w;

    float sgm = g.x + g.y + g.z + g.w;
#pragma unroll
    for (int m = 16; m; m >>= 1) sgm += __shfl_xor_sync(0xffffffffu, sgm, m);
    float mu = sgm * (1.f / 128.f);

    float dx = g.x - mu, dy = g.y - mu, dz = g.z - mu, dw = g.w - mu;
    float vs = dx * dx + dy * dy + dz * dz + dw * dw;
#pragma unroll
    for (int m = 16; m; m >>= 1) vs += __shfl_xor_sync(0xffffffffu, vs, m);
    float rstd = rsqrtf(vs * (1.f / 128.f) + 1e-5f);

    float4 gm = *(const float4*)(gamma + c);
    float4 lb = *(const float4*)(lbeta + c);
    float4 xin = *(const float4*)(x + (size_t)n * HID + c);

    float4 res;
    float y;
    y = dx * rstd * gm.x + lb.x; res.x = xin.x + fmaxf(y, 0.f);
    y = dy * rstd * gm.y + lb.y; res.y = xin.y + fmaxf(y, 0.f);
    y = dz * rstd * gm.z + lb.z; res.z = xin.z + fmaxf(y, 0.f);
    y = dw * rstd * gm.w + lb.w; res.w = xin.w + fmaxf(y, 0.f);
    *(float4*)(out + (size_t)n * HID + c) = res;
}

// ---------------- launch ----------------
extern "C" void kernel_launch(void* const* d_in, const int* in_sizes, int n_in,
                              void* d_out, int out_size)
{
    const float* edge_state = (const float*)d_in[0];
    const void*  idx        = d_in[1];
    const float* angle      = (const float*)d_in[2];
    const float* Wq = (const float*)d_in[3];
    const float* bq = (const float*)d_in[4];
    const float* Wk = (const float*)d_in[5];
    const float* bk = (const float*)d_in[6];
    const float* Wv = (const float*)d_in[7];
    const float* bv = (const float*)d_in[8];
    const float* We = (const float*)d_in[9];
    const float* Ws = (const float*)d_in[10];
    const float* bs = (const float*)d_in[11];
    const float* Wbeta = (const float*)d_in[12];
    const float* gamma = (const float*)d_in[13];
    const float* lbeta = (const float*)d_in[14];

    int N = in_sizes[0] / HID;
    int E = in_sizes[2] / HID;
    int eTiles = (E + 63) / 64;
    int nTiles = (N + 63) / 64;
    int egrid = 296;                 // 2 persistent CTAs per SM
    int ngrid = 296;
    if (egrid > eTiles) egrid = eTiles;
    if (ngrid > nTiles) ngrid = nTiles;

    cudaFuncSetAttribute(node_pipe_kernel, cudaFuncAttributeMaxDynamicSharedMemorySize, ESM_TOTAL);
    cudaFuncSetAttribute(egemm_pipe_kernel, cudaFuncAttributeMaxDynamicSharedMemorySize, ESM_TOTAL);

    // launch order: egemm is the 4th launch so the ncu capture slot lands on it
    detect_kernel<<<1, 32>>>(idx, (long long)in_sizes[1]);
    prep_w_kernel<<<5, 128>>>(Wq, Wk, Wv, Ws, We);
    zero_deg_kernel<<<(N + 255) / 256, 256>>>(N);

    egemm_pipe_kernel<<<egrid, 256, ESM_TOTAL>>>(angle, E, eTiles);   // 4th

    count_kernel<<<(E + 255) / 256, 256>>>(idx, E);
    scan_kernel<<<1, 1024>>>(N, E);
    scatter_kernel<<<(E + 255) / 256, 256>>>(idx, E);

    node_pipe_kernel<<<ngrid, 256, ESM_TOTAL>>>(edge_state, bq, bk, bv, bs, N, nTiles);

    attn_gather_kernel<<<(N + 7) / 8, 256>>>(N);

    finalize_kernel<<<(N + 7) / 8, 256>>>(edge_state, Wbeta, gamma, lbeta,
                                          (float*)d_out, N);
}